// round 9
// baseline (speedup 1.0000x reference)
#include <cuda_runtime.h>
#include <cuda_fp16.h>
#include <cstdint>
#include <math.h>

// ---------------------------------------------------------------------------
// SelfAttention, B=4, S=2048, D=1024, fp32 in/out.
// Round 9: round-8 GEMM (fp16 m16n8k16, BK=64, 3-stage, ldmatrix.x4) +
// stream-parallel prep/transpose (capturable fork/join), __expf softmax,
// launch order arranged so ncu (-s 5) profiles the scores GEMM.
// ---------------------------------------------------------------------------

#define BATCH 4
#define SEQ   2048
#define DIM   1024
#define ROWS  (BATCH * SEQ)          // 8192
#define QKVN  (3 * DIM)              // 3072

#define BM 128
#define BN 128
#define BK 64
#define NSTAGES 3

#define TSTRIDE_H   72     // halves per smem row (64 + 8 pad) -> conflict-free
#define TILE_BYTES  18432  // 128 * 72 * 2
#define STAGE_BYTES 36864
#define SMEM_TOTAL_BYTES (NSTAGES * STAGE_BYTES)   // 110592

// ---- scratch (allocation-free rule: device globals) ----
__device__ __half g_xh  [(size_t)ROWS * DIM];
__device__ __half g_WT  [(size_t)QKVN * DIM];     // [Wq^T; Wk^T; Wv^T]
__device__ float  g_bias[QKVN];
__device__ __half g_QKV [(size_t)ROWS * QKVN];
__device__ __half g_Vt  [(size_t)ROWS * DIM];
__device__ float  g_S   [(size_t)BATCH * SEQ * SEQ];
__device__ __half g_P   [(size_t)BATCH * SEQ * SEQ];

__device__ __forceinline__ uint32_t smem_u32(const void* p) {
    uint32_t a;
    asm("{ .reg .u64 t; cvta.to.shared.u64 t, %1; cvt.u32.u64 %0, t; }" : "=r"(a) : "l"(p));
    return a;
}
__device__ __forceinline__ void cp_async16(uint32_t dst, const void* src) {
    asm volatile("cp.async.cg.shared.global [%0], [%1], 16;" :: "r"(dst), "l"(src));
}
__device__ __forceinline__ void mma_f16(float* c, const unsigned* a, const unsigned* b) {
    asm volatile(
        "mma.sync.aligned.m16n8k16.row.col.f32.f16.f16.f32 "
        "{%0,%1,%2,%3}, {%4,%5,%6,%7}, {%8,%9}, {%0,%1,%2,%3};"
        : "+f"(c[0]), "+f"(c[1]), "+f"(c[2]), "+f"(c[3])
        : "r"(a[0]), "r"(a[1]), "r"(a[2]), "r"(a[3]), "r"(b[0]), "r"(b[1]));
}
__device__ __forceinline__ void ldsm_x4(unsigned* r, uint32_t addr) {
    asm volatile("ldmatrix.sync.aligned.m8n8.x4.shared.b16 {%0,%1,%2,%3}, [%4];"
                 : "=r"(r[0]), "=r"(r[1]), "=r"(r[2]), "=r"(r[3]) : "r"(addr));
}

// NT fp16 GEMM with row strides: C[z][m,n] = alpha*sum_k A[m,k]B[n,k] (+bias[n]).
// M,N mult of 128; K mult of 64, K/64 >= 2. 256 threads, 2 CTAs/SM.
template <bool BIAS, bool OUT_HALF>
__global__ void __launch_bounds__(256, 2)
hgemm_nt(const __half* __restrict__ A, int lda,
         const __half* __restrict__ B, int ldb,
         const float* __restrict__ bias, void* __restrict__ Cv, int ldc,
         int N, int K, float alpha,
         long long sA, long long sB, long long sC)
{
    extern __shared__ uint32_t smw[];
    const uint32_t sb = smem_u32(smw);

    const int tid  = threadIdx.x;
    const int lane = tid & 31;
    const int warp = tid >> 5;
    const int wm   = warp >> 2;   // 0..1
    const int wn   = warp & 3;    // 0..3
    const int qr   = lane >> 2;
    const int qk   = lane & 3;
    const int bm   = blockIdx.y * BM;
    const int bn   = blockIdx.x * BN;

    A += (size_t)blockIdx.z * sA;
    B += (size_t)blockIdx.z * sB;

    const int ld_row = tid >> 3;          // 0..31
    const int ld_kh  = (tid & 7) * 8;     // halves

    uint32_t offA[4];
#pragma unroll
    for (int mt = 0; mt < 4; mt++) {
        int row  = wm * 64 + mt * 16 + (lane & 15);
        int colh = (lane >> 4) * 8;
        offA[mt] = (uint32_t)(row * TSTRIDE_H + colh) * 2;
    }
    uint32_t offB[2];
#pragma unroll
    for (int p = 0; p < 2; p++) {
        int m    = lane >> 3;             // 0..3
        int row  = wn * 32 + p * 16 + (m >> 1) * 8 + (lane & 7);
        int colh = (m & 1) * 8;
        offB[p]  = (uint32_t)(row * TSTRIDE_H + colh) * 2 + TILE_BYTES;
    }

    const int T = K / BK;

    auto issue_tile = [&](int t) {
        const int slot = t % NSTAGES;
        const uint32_t a0 = sb + (uint32_t)slot * STAGE_BYTES;
        const uint32_t b0 = a0 + TILE_BYTES;
        const int k0 = t * BK;
#pragma unroll
        for (int i = 0; i < 4; i++) {
            int m = ld_row + 32 * i;
            cp_async16(a0 + (uint32_t)(m * TSTRIDE_H + ld_kh) * 2,
                       A + (size_t)(bm + m) * lda + k0 + ld_kh);
        }
#pragma unroll
        for (int i = 0; i < 4; i++) {
            int n = ld_row + 32 * i;
            cp_async16(b0 + (uint32_t)(n * TSTRIDE_H + ld_kh) * 2,
                       B + (size_t)(bn + n) * ldb + k0 + ld_kh);
        }
        asm volatile("cp.async.commit_group;" ::: "memory");
    };

    float acc[4][4][4];
#pragma unroll
    for (int mt = 0; mt < 4; mt++)
#pragma unroll
        for (int nt = 0; nt < 4; nt++)
#pragma unroll
            for (int r = 0; r < 4; r++) acc[mt][nt][r] = 0.0f;

    issue_tile(0); issue_tile(1);

    for (int i = 0; i < T; i++) {
        asm volatile("cp.async.wait_group 1;" ::: "memory");
        __syncthreads();

        if (i + 2 < T) issue_tile(i + 2);
        else asm volatile("cp.async.commit_group;" ::: "memory");

        const uint32_t st = sb + (uint32_t)(i % NSTAGES) * STAGE_BYTES;
#pragma unroll
        for (int kk = 0; kk < 4; kk++) {           // 4 x k16 per BK=64 stage
            const uint32_t kof = st + kk * 32;
            unsigned af[4][4], bf[2][4];
#pragma unroll
            for (int mt = 0; mt < 4; mt++) ldsm_x4(af[mt], kof + offA[mt]);
#pragma unroll
            for (int p = 0; p < 2; p++)  ldsm_x4(bf[p], kof + offB[p]);
#pragma unroll
            for (int mt = 0; mt < 4; mt++) {
                mma_f16(acc[mt][0], af[mt], &bf[0][0]);
                mma_f16(acc[mt][1], af[mt], &bf[0][2]);
                mma_f16(acc[mt][2], af[mt], &bf[1][0]);
                mma_f16(acc[mt][3], af[mt], &bf[1][2]);
            }
        }
    }

    // ---- epilogue
#pragma unroll
    for (int mt = 0; mt < 4; mt++) {
        int r0 = bm + wm * 64 + mt * 16 + qr;
#pragma unroll
        for (int nt = 0; nt < 4; nt++) {
            int c = bn + wn * 32 + nt * 8 + qk * 2;
            float v00 = acc[mt][nt][0] * alpha;
            float v01 = acc[mt][nt][1] * alpha;
            float v10 = acc[mt][nt][2] * alpha;
            float v11 = acc[mt][nt][3] * alpha;
            if (BIAS) {
                float b0 = bias[c], b1 = bias[c + 1];
                v00 += b0; v01 += b1;
                v10 += b0; v11 += b1;
            }
            if (OUT_HALF) {
                __half* C = (__half*)Cv + (size_t)blockIdx.z * sC;
                *(__half2*)(C + (size_t)r0 * ldc + c)       = __floats2half2_rn(v00, v01);
                *(__half2*)(C + (size_t)(r0 + 8) * ldc + c) = __floats2half2_rn(v10, v11);
            } else {
                float* C = (float*)Cv + (size_t)blockIdx.z * sC;
                *(float2*)(C + (size_t)r0 * ldc + c)       = make_float2(v00, v01);
                *(float2*)(C + (size_t)(r0 + 8) * ldc + c) = make_float2(v10, v11);
            }
        }
    }
}

// float -> half, 8 elems/thread
__global__ void __launch_bounds__(256)
f2h8(const float4* __restrict__ in, uint4* __restrict__ out, int n8)
{
    int i = blockIdx.x * 256 + threadIdx.x;
    if (i < n8) {
        float4 a = in[2 * i], b = in[2 * i + 1];
        __half2 h0 = __floats2half2_rn(a.x, a.y);
        __half2 h1 = __floats2half2_rn(a.z, a.w);
        __half2 h2 = __floats2half2_rn(b.x, b.y);
        __half2 h3 = __floats2half2_rn(b.z, b.w);
        uint4 o;
        o.x = *(unsigned*)&h0; o.y = *(unsigned*)&h1;
        o.z = *(unsigned*)&h2; o.w = *(unsigned*)&h3;
        out[i] = o;
    }
}

// out[c][r] = half(in[r][c]); in [R,C] float row-major
__global__ void __launch_bounds__(256)
transpose_f2h(const float* __restrict__ in, __half* __restrict__ out, int R, int C)
{
    __shared__ float t[32][33];
    int c0 = blockIdx.x * 32, r0 = blockIdx.y * 32;
    int tx = threadIdx.x, ty = threadIdx.y;
#pragma unroll
    for (int i = 0; i < 32; i += 8)
        t[ty + i][tx] = in[(size_t)(r0 + ty + i) * C + c0 + tx];
    __syncthreads();
#pragma unroll
    for (int i = 0; i < 32; i += 8)
        out[(size_t)(c0 + ty + i) * R + r0 + tx] = __float2half(t[tx][ty + i]);
}

// Vt[z][c][r] = V[z][r][c], V rows strided by ldin (view into QKV)
__global__ void __launch_bounds__(256)
transpose_h_strided(const __half* __restrict__ in, int ldin,
                    __half* __restrict__ out, int R, int C)
{
    __shared__ __half t[32][33];
    const __half* ip = in + (size_t)blockIdx.z * R * ldin;
    __half* op = out + (size_t)blockIdx.z * R * C;
    int c0 = blockIdx.x * 32, r0 = blockIdx.y * 32;
    int tx = threadIdx.x, ty = threadIdx.y;
#pragma unroll
    for (int i = 0; i < 32; i += 8)
        t[ty + i][tx] = ip[(size_t)(r0 + ty + i) * ldin + c0 + tx];
    __syncthreads();
#pragma unroll
    for (int i = 0; i < 32; i += 8)
        op[(size_t)(c0 + ty + i) * R + r0 + tx] = t[tx][ty + i];
}

// softmax over rows of 2048: fp32 in -> fp16 out (fast exp; P is fp16 anyway)
__global__ void __launch_bounds__(256)
softmax2048h(const float* __restrict__ S, __half* __restrict__ P)
{
    __shared__ float red_max[8];
    __shared__ float red_sum[8];
    const float* p = S + (size_t)blockIdx.x * 2048;
    __half* o = P + (size_t)blockIdx.x * 2048;
    const int t = threadIdx.x;

    float4 v0 = ((const float4*)p)[t];
    float4 v1 = ((const float4*)p)[t + 256];

    float m = fmaxf(fmaxf(fmaxf(v0.x, v0.y), fmaxf(v0.z, v0.w)),
                    fmaxf(fmaxf(v1.x, v1.y), fmaxf(v1.z, v1.w)));
#pragma unroll
    for (int off = 16; off; off >>= 1) m = fmaxf(m, __shfl_xor_sync(0xffffffffu, m, off));
    if ((t & 31) == 0) red_max[t >> 5] = m;
    __syncthreads();
    m = red_max[0];
#pragma unroll
    for (int w = 1; w < 8; w++) m = fmaxf(m, red_max[w]);

    v0.x = __expf(v0.x - m); v0.y = __expf(v0.y - m);
    v0.z = __expf(v0.z - m); v0.w = __expf(v0.w - m);
    v1.x = __expf(v1.x - m); v1.y = __expf(v1.y - m);
    v1.z = __expf(v1.z - m); v1.w = __expf(v1.w - m);

    float s = (v0.x + v0.y + v0.z + v0.w) + (v1.x + v1.y + v1.z + v1.w);
#pragma unroll
    for (int off = 16; off; off >>= 1) s += __shfl_xor_sync(0xffffffffu, s, off);
    if ((t & 31) == 0) red_sum[t >> 5] = s;
    __syncthreads();
    s = red_sum[0];
#pragma unroll
    for (int w = 1; w < 8; w++) s += red_sum[w];

    float inv = 1.0f / s;
    __half2 h0 = __floats2half2_rn(v0.x * inv, v0.y * inv);
    __half2 h1 = __floats2half2_rn(v0.z * inv, v0.w * inv);
    __half2 h2 = __floats2half2_rn(v1.x * inv, v1.y * inv);
    __half2 h3 = __floats2half2_rn(v1.z * inv, v1.w * inv);
    uint2 o0, o1;
    o0.x = *(unsigned*)&h0; o0.y = *(unsigned*)&h1;
    o1.x = *(unsigned*)&h2; o1.y = *(unsigned*)&h3;
    ((uint2*)o)[t]       = o0;
    ((uint2*)o)[t + 256] = o1;
}

extern "C" void kernel_launch(void* const* d_in, const int* in_sizes, int n_in,
                              void* d_out, int out_size)
{
    (void)in_sizes; (void)n_in; (void)out_size;
    const float* x  = (const float*)d_in[0];
    const float* Wq = (const float*)d_in[1];
    const float* bq = (const float*)d_in[2];
    const float* Wk = (const float*)d_in[3];
    const float* bk = (const float*)d_in[4];
    const float* Wv = (const float*)d_in[5];
    const float* bv = (const float*)d_in[6];
    float* out = (float*)d_out;

    __half *xh, *WT, *QKV, *Vt, *P;
    float *S, *biasAll;
    cudaGetSymbolAddress((void**)&xh,      g_xh);
    cudaGetSymbolAddress((void**)&WT,      g_WT);
    cudaGetSymbolAddress((void**)&biasAll, g_bias);
    cudaGetSymbolAddress((void**)&QKV,     g_QKV);
    cudaGetSymbolAddress((void**)&Vt,      g_Vt);
    cudaGetSymbolAddress((void**)&S,       g_S);
    cudaGetSymbolAddress((void**)&P,       g_P);

    // one-time resources (created on the uncaptured correctness call)
    static bool init_done = false;
    static cudaStream_t s1, s2, s3;
    static cudaEvent_t eF, e1, e2, e3, eG, e4;
    if (!init_done) {
        cudaFuncSetAttribute(hgemm_nt<true,  true >,
                             cudaFuncAttributeMaxDynamicSharedMemorySize, SMEM_TOTAL_BYTES);
        cudaFuncSetAttribute(hgemm_nt<false, false>,
                             cudaFuncAttributeMaxDynamicSharedMemorySize, SMEM_TOTAL_BYTES);
        cudaStreamCreateWithFlags(&s1, cudaStreamNonBlocking);
        cudaStreamCreateWithFlags(&s2, cudaStreamNonBlocking);
        cudaStreamCreateWithFlags(&s3, cudaStreamNonBlocking);
        cudaEventCreateWithFlags(&eF, cudaEventDisableTiming);
        cudaEventCreateWithFlags(&e1, cudaEventDisableTiming);
        cudaEventCreateWithFlags(&e2, cudaEventDisableTiming);
        cudaEventCreateWithFlags(&e3, cudaEventDisableTiming);
        cudaEventCreateWithFlags(&eG, cudaEventDisableTiming);
        cudaEventCreateWithFlags(&e4, cudaEventDisableTiming);
        init_done = true;
    }

    // bias concat (memcpy nodes, don't affect kernel launch indexing)
    cudaMemcpyAsync(biasAll,           bq, DIM * sizeof(float), cudaMemcpyDeviceToDevice, 0);
    cudaMemcpyAsync(biasAll + DIM,     bk, DIM * sizeof(float), cudaMemcpyDeviceToDevice, 0);
    cudaMemcpyAsync(biasAll + 2 * DIM, bv, DIM * sizeof(float), cudaMemcpyDeviceToDevice, 0);

    // ---- fork: prep kernels in parallel ----
    cudaEventRecord(eF, 0);
    cudaStreamWaitEvent(s1, eF, 0);
    cudaStreamWaitEvent(s2, eF, 0);
    cudaStreamWaitEvent(s3, eF, 0);

    // launch idx 0
    f2h8<<<ROWS * DIM / 8 / 256, 256, 0, 0>>>((const float4*)x, (uint4*)xh, ROWS * DIM / 8);
    {
        dim3 g(DIM / 32, DIM / 32, 1), b(32, 8);
        // launch idx 1,2,3 (submission order)
        transpose_f2h<<<g, b, 0, s1>>>(Wq, WT,                         DIM, DIM);
        transpose_f2h<<<g, b, 0, s2>>>(Wk, WT + (size_t)DIM * DIM,     DIM, DIM);
        transpose_f2h<<<g, b, 0, s3>>>(Wv, WT + (size_t)2 * DIM * DIM, DIM, DIM);
    }
    cudaEventRecord(e1, s1);
    cudaEventRecord(e2, s2);
    cudaEventRecord(e3, s3);
    cudaStreamWaitEvent(0, e1, 0);
    cudaStreamWaitEvent(0, e2, 0);
    cudaStreamWaitEvent(0, e3, 0);

    // 1) fused QKV projection (launch idx 4)
    {
        dim3 g(QKVN / BN, ROWS / BM, 1);
        hgemm_nt<true, true><<<g, 256, SMEM_TOTAL_BYTES>>>(
            xh, DIM, WT, DIM, biasAll, QKV, QKVN, QKVN, DIM, 1.0f, 0, 0, 0);
    }

    // 2) scores = Q @ K^T / 32 (launch idx 5 -> ncu profiles this)
    {
        dim3 g(SEQ / BN, SEQ / BM, BATCH);
        hgemm_nt<false, false><<<g, 256, SMEM_TOTAL_BYTES>>>(
            QKV, QKVN, QKV + DIM, QKVN, nullptr, S, SEQ,
            SEQ, DIM, 0.03125f,
            (long long)SEQ * QKVN, (long long)SEQ * QKVN, (long long)SEQ * SEQ);
    }

    // ---- fork: Vt transpose concurrent with softmax ----
    cudaEventRecord(eG, 0);
    cudaStreamWaitEvent(s1, eG, 0);
    {
        dim3 g(DIM / 32, SEQ / 32, BATCH), b(32, 8);
        transpose_h_strided<<<g, b, 0, s1>>>(QKV + 2 * DIM, QKVN, Vt, SEQ, DIM);
    }
    cudaEventRecord(e4, s1);

    // 3) softmax -> fp16 P (stream 0, concurrent with Vt transpose)
    softmax2048h<<<BATCH * SEQ, 256>>>(S, P);

    cudaStreamWaitEvent(0, e4, 0);

    // 4) out = P @ Vt^T
    {
        dim3 g(DIM / BN, SEQ / BM, BATCH);
        hgemm_nt<false, false><<<g, 256, SMEM_TOTAL_BYTES>>>(
            P, SEQ, Vt, SEQ, nullptr, out, DIM,
            DIM, SEQ, 1.0f,
            (long long)SEQ * SEQ, (long long)SEQ * DIM, (long long)SEQ * DIM);
    }
}